// round 1
// baseline (speedup 1.0000x reference)
#include <cuda_runtime.h>

// Depthwise 5x5 blur, x: (32,128,128,128) fp32 -> treated as 4096 images of 128x128.
// Weights: w[i][j] = exp(-((di^2+dj^2)^2) / (2*exp(log_ls))), normalized to sum 1.

#define KW 5
#define RAD 2
#define TH 16          // output rows per block
#define WID 128        // image width/height
#define SH (TH + 4)    // 20 smem rows
#define SW (WID + 4)   // 132 smem cols

__device__ float g_w[25];

__global__ void blur_weights_kernel(const float* __restrict__ logls) {
    __shared__ float wraw[25];
    int t = threadIdx.x;
    float ls = expf(logls[0]);
    if (t < 25) {
        int di = t / 5 - RAD;
        int dj = t % 5 - RAD;
        float d = (float)(di * di + dj * dj);
        float d2 = d * d;
        wraw[t] = expf(-d2 / (2.0f * ls));
    }
    __syncthreads();
    if (t == 0) {
        float s = 0.0f;
        #pragma unroll
        for (int u = 0; u < 25; u++) s += wraw[u];
        float inv = 1.0f / s;
        #pragma unroll
        for (int u = 0; u < 25; u++) g_w[u] = wraw[u] * inv;
    }
}

__global__ void __launch_bounds__(256, 2)
blur_main_kernel(const float* __restrict__ x, float* __restrict__ out) {
    __shared__ float tile[SH][SW];
    __shared__ float wsh[25];

    const int tid  = threadIdx.x;
    const int img  = blockIdx.y;
    const int row0 = blockIdx.x * TH;

    if (tid < 25) wsh[tid] = g_w[tid];

    const float* __restrict__ base = x + (size_t)img * (WID * WID);

    // Cooperative tile load with zero-padded halo (2 on each side).
    #pragma unroll 4
    for (int idx = tid; idx < SH * SW; idx += 256) {
        int r = idx / SW;
        int c = idx - r * SW;
        int gr = row0 + r - RAD;
        int gc = c - RAD;
        float v = 0.0f;
        if (gr >= 0 && gr < WID && gc >= 0 && gc < WID)
            v = base[gr * WID + gc];
        tile[r][c] = v;
    }
    __syncthreads();

    // Thread mapping: col = tid & 127 (one column each), half = tid >> 7
    // selects rows [half*8, half*8+8).
    const int col  = tid & (WID - 1);
    const int half = tid >> 7;
    const int r0   = half * 8;

    // Weights into registers.
    float w[25];
    #pragma unroll
    for (int u = 0; u < 25; u++) w[u] = wsh[u];

    // Register window: 12 rows x 5 cols covers the 8 outputs of this column.
    float v[12][5];
    #pragma unroll
    for (int i = 0; i < 12; i++) {
        #pragma unroll
        for (int j = 0; j < 5; j++) {
            v[i][j] = tile[r0 + i][col + j];
        }
    }

    float* __restrict__ o = out + (size_t)img * (WID * WID) + (row0 + r0) * WID + col;

    #pragma unroll
    for (int i = 0; i < 8; i++) {
        float acc = 0.0f;
        #pragma unroll
        for (int dy = 0; dy < 5; dy++) {
            #pragma unroll
            for (int dx = 0; dx < 5; dx++) {
                acc = fmaf(w[dy * 5 + dx], v[i + dy][dx], acc);
            }
        }
        o[i * WID] = acc;
    }
}

extern "C" void kernel_launch(void* const* d_in, const int* in_sizes, int n_in,
                              void* d_out, int out_size) {
    const float* x     = (const float*)d_in[0];
    const float* logls = (const float*)d_in[1];
    float* out = (float*)d_out;

    blur_weights_kernel<<<1, 32>>>(logls);

    dim3 grid(WID / TH, 32 * 128);  // 8 x 4096
    blur_main_kernel<<<grid, 256>>>(x, out);
}

// round 2
// speedup vs baseline: 1.6298x; 1.6298x over previous
#include <cuda_runtime.h>

// Depthwise 5x5 blur, x: (32,128,128,128) fp32 = 4096 images of 128x128.
// w[dy][dx] = exp(-((dy^2+dx^2)^2)/(2*exp(log_ls))), normalized. Fully symmetric.

#define RAD 2
#define TH  32          // output rows per block
#define WID 128
#define SH  (TH + 4)    // 36 smem rows
#define SW  (WID + 4)   // 132 smem cols (cols 0,1,130,131 are constant-zero halo)

__device__ float g_w[25];

__global__ void blur_weights_kernel(const float* __restrict__ logls) {
    __shared__ float wraw[25];
    int t = threadIdx.x;
    float ls = expf(logls[0]);
    if (t < 25) {
        int di = t / 5 - RAD;
        int dj = t % 5 - RAD;
        float d = (float)(di * di + dj * dj);
        wraw[t] = expf(-(d * d) / (2.0f * ls));
    }
    __syncthreads();
    if (t == 0) {
        float s = 0.0f;
        #pragma unroll
        for (int u = 0; u < 25; u++) s += wraw[u];
        float inv = 1.0f / s;
        #pragma unroll
        for (int u = 0; u < 25; u++) g_w[u] = wraw[u] * inv;
    }
}

typedef unsigned long long u64;

__device__ __forceinline__ u64 pk(float lo, float hi) {
    u64 r; asm("mov.b64 %0, {%1, %2};" : "=l"(r) : "f"(lo), "f"(hi)); return r;
}
__device__ __forceinline__ u64 add2(u64 a, u64 b) {
    u64 r; asm("add.rn.f32x2 %0, %1, %2;" : "=l"(r) : "l"(a), "l"(b)); return r;
}
__device__ __forceinline__ void fma2(u64& d, u64 a, u64 b) {
    asm("fma.rn.f32x2 %0, %1, %2, %0;" : "+l"(d) : "l"(a), "l"(b));
}
__device__ __forceinline__ float2 unpk(u64 a) {
    float2 v; asm("mov.b64 {%0, %1}, %2;" : "=f"(v.x), "=f"(v.y) : "l"(a)); return v;
}

__global__ void __launch_bounds__(256, 3)
blur_main_kernel(const float* __restrict__ x, float* __restrict__ out) {
    __shared__ __align__(16) float tile[SH][SW];
    __shared__ float wsh[25];

    const int tid  = threadIdx.x;
    const int img  = blockIdx.y;
    const int row0 = blockIdx.x * TH;

    if (tid < 25) wsh[tid] = g_w[tid];

    // Column halos are always outside the image -> constant zero.
    if (tid < SH * 4) {
        int r  = tid >> 2;
        int cc = tid & 3;
        int col = (cc < 2) ? cc : (cc + 128);   // 0,1,130,131
        tile[r][col] = 0.0f;
    }

    const float* __restrict__ base = x + (size_t)img * (WID * WID);

    // Interior: 36 rows x 32 float4 per row, fully coalesced LDG.128.
    #pragma unroll
    for (int it = 0; it < 5; it++) {
        int idx = tid + it * 256;
        if (idx < SH * 32) {
            int r  = idx >> 5;
            int c4 = idx & 31;
            int gr = row0 + r - RAD;
            float4 v = make_float4(0.f, 0.f, 0.f, 0.f);
            if (gr >= 0 && gr < WID)
                v = *(const float4*)(base + gr * WID + c4 * 4);
            float* dst = &tile[r][2 + c4 * 4];     // byte offset 8 mod 16 -> 2x STS.64
            *(float2*)(dst)     = make_float2(v.x, v.y);
            *(float2*)(dst + 2) = make_float2(v.z, v.w);
        }
    }
    __syncthreads();

    // Packed duplicated weights; rows 3,4 mirror rows 1,0; cols 3,4 mirror 1,0.
    u64 wp[3][3];
    #pragma unroll
    for (int k = 0; k < 3; k++) {
        wp[k][0] = pk(wsh[k * 5 + 0], wsh[k * 5 + 0]);  // |dx|=2
        wp[k][1] = pk(wsh[k * 5 + 1], wsh[k * 5 + 1]);  // |dx|=1
        wp[k][2] = pk(wsh[k * 5 + 2], wsh[k * 5 + 2]);  // dx=0
    }

    // Each thread: 4 output rows x 4 output cols.
    const int c  = (tid & 31) * 4;        // output col (0..124)
    const int rg = (tid >> 5) * 4;        // output row group within tile

    u64 acc0[4], acc1[4];                 // (o_c,o_c+1), (o_c+2,o_c+3) per row
    #pragma unroll
    for (int i = 0; i < 4; i++) { acc0[i] = 0ull; acc1[i] = 0ull; }

    #pragma unroll
    for (int ir = 0; ir < 8; ir++) {      // 8 input rows cover 4 outputs + halo
        const float* rp = &tile[rg + ir][c];   // 16B-aligned
        float4 a = *(const float4*)rp;         // x0..x3
        float4 b = *(const float4*)(rp + 4);   // x4..x7
        u64 p23 = pk(a.z, a.w);
        u64 p45 = pk(b.x, b.y);
        u64 p34 = pk(a.w, b.x);
        u64 t1a = add2(pk(a.x, a.y), p45);          // (x0+x4, x1+x5)
        u64 t2a = add2(pk(a.y, a.z), p34);          // (x1+x3, x2+x4)
        u64 t1b = add2(p23, pk(b.z, b.w));          // (x2+x6, x3+x7)
        u64 t2b = add2(p34, pk(b.y, b.z));          // (x3+x5, x4+x6)
        #pragma unroll
        for (int orow = 0; orow < 4; orow++) {
            int dy = ir - orow;
            if (dy < 0 || dy > 4) continue;
            int k = (dy < 3) ? dy : 4 - dy;         // row symmetry
            fma2(acc0[orow], wp[k][0], t1a);
            fma2(acc0[orow], wp[k][1], t2a);
            fma2(acc0[orow], wp[k][2], p23);
            fma2(acc1[orow], wp[k][0], t1b);
            fma2(acc1[orow], wp[k][1], t2b);
            fma2(acc1[orow], wp[k][2], p45);
        }
    }

    float* op = out + (size_t)img * (WID * WID) + (size_t)(row0 + rg) * WID + c;
    #pragma unroll
    for (int orow = 0; orow < 4; orow++) {
        float2 lo = unpk(acc0[orow]);
        float2 hi = unpk(acc1[orow]);
        *(float4*)(op + orow * WID) = make_float4(lo.x, lo.y, hi.x, hi.y);
    }
}

extern "C" void kernel_launch(void* const* d_in, const int* in_sizes, int n_in,
                              void* d_out, int out_size) {
    const float* x     = (const float*)d_in[0];
    const float* logls = (const float*)d_in[1];
    float* out = (float*)d_out;

    blur_weights_kernel<<<1, 32>>>(logls);

    dim3 grid(WID / TH, 32 * 128);   // 4 x 4096
    blur_main_kernel<<<grid, 256>>>(x, out);
}

// round 3
// speedup vs baseline: 1.7491x; 1.0732x over previous
#include <cuda_runtime.h>

// Depthwise 5x5 blur, x: (32,128,128,128) fp32 = 4096 images of 128x128.
// w[dy][dx] = exp(-((dy^2+dx^2)^2)/(2*exp(log_ls))), normalized. Fully symmetric:
// only 3 distinct row-classes (k = min(dy,4-dy)) x 3 col-classes.

#define RAD 2
#define WID 128
#define STRIP 32        // output rows per thread

__device__ float g_w[25];

__global__ void blur_weights_kernel(const float* __restrict__ logls) {
    __shared__ float wraw[25];
    int t = threadIdx.x;
    float ls = expf(logls[0]);
    if (t < 25) {
        int di = t / 5 - RAD;
        int dj = t % 5 - RAD;
        float d = (float)(di * di + dj * dj);
        wraw[t] = expf(-(d * d) / (2.0f * ls));
    }
    __syncthreads();
    if (t == 0) {
        float s = 0.0f;
        #pragma unroll
        for (int u = 0; u < 25; u++) s += wraw[u];
        float inv = 1.0f / s;
        #pragma unroll
        for (int u = 0; u < 25; u++) g_w[u] = wraw[u] * inv;
    }
}

typedef unsigned long long u64;

__device__ __forceinline__ u64 pk(float lo, float hi) {
    u64 r; asm("mov.b64 %0, {%1, %2};" : "=l"(r) : "f"(lo), "f"(hi)); return r;
}
__device__ __forceinline__ u64 add2(u64 a, u64 b) {
    u64 r; asm("add.rn.f32x2 %0, %1, %2;" : "=l"(r) : "l"(a), "l"(b)); return r;
}
__device__ __forceinline__ void fma2(u64& d, u64 a, u64 b) {
    asm("fma.rn.f32x2 %0, %1, %2, %0;" : "+l"(d) : "l"(a), "l"(b));
}
__device__ __forceinline__ float2 unpk(u64 a) {
    float2 v; asm("mov.b64 {%0, %1}, %2;" : "=f"(v.x), "=f"(v.y) : "l"(a)); return v;
}

// Thread layout: lane = tid&31 -> 4 output cols (c = lane*4);
// strip = (tid>>5)&3 -> 32 output rows; (tid>>7) selects image within block.
// Block = 256 threads = 2 images. Grid = 2048 blocks. No shared memory.
__global__ void __launch_bounds__(256, 3)
blur_main_kernel(const float* __restrict__ x, float* __restrict__ out) {
    const int tid   = threadIdx.x;
    const int lane  = tid & 31;
    const int strip = (tid >> 5) & 3;
    const int img   = blockIdx.x * 2 + (tid >> 7);
    const int c     = lane * 4;
    const int row0  = strip * STRIP;

    // Packed duplicated weights: wp[k][0]=|dx|2, [1]=|dx|1, [2]=dx0.
    u64 wp[3][3];
    #pragma unroll
    for (int k = 0; k < 3; k++) {
        float w0 = g_w[k * 5 + 0];
        float w1 = g_w[k * 5 + 1];
        float w2 = g_w[k * 5 + 2];
        wp[k][0] = pk(w0, w0);
        wp[k][1] = pk(w1, w1);
        wp[k][2] = pk(w2, w2);
    }

    const float* __restrict__ base = x + (size_t)img * (WID * WID);
    const float* rowp = base + (row0 - RAD) * WID + c;
    float*       outp = out + (size_t)img * (WID * WID) + row0 * WID + c;

    const bool has_l = (lane > 0);    // cols c-2,c-1 exist
    const bool has_h = (lane < 31);   // cols c+4,c+5 exist

    // Ring of 6 accumulator pairs (5 live at a time).
    u64 acc0[6], acc1[6];
    #pragma unroll
    for (int i = 0; i < 6; i++) { acc0[i] = 0ull; acc1[i] = 0ull; }

    #pragma unroll
    for (int r = 0; r < STRIP + 4; r++) {
        const int gr = row0 + r - RAD;           // only strips 0/3 can be OOB
        const bool vr = ((unsigned)gr < (unsigned)WID);

        float4 a = make_float4(0.f, 0.f, 0.f, 0.f);
        float2 l = make_float2(0.f, 0.f);
        float2 h = make_float2(0.f, 0.f);
        if (vr) {
            a = *(const float4*)(rowp);
            if (has_l) l = *(const float2*)(rowp - 2);
            if (has_h) h = *(const float2*)(rowp + 4);
        }
        rowp += WID;

        // Horizontal pair-sums for output cols (c,c+1) and (c+2,c+3).
        // x[-2..5] = l.x,l.y, a.x,a.y,a.z,a.w, h.x,h.y
        u64 p01 = pk(a.x, a.y);
        u64 p23 = pk(a.z, a.w);
        u64 t1a = add2(pk(l.x, l.y), p23);             // (x-2+x2, x-1+x3)
        u64 t2a = add2(pk(l.y, a.x), pk(a.y, a.z));    // (x-1+x1, x0+x2)
        u64 t1b = add2(p01, pk(h.x, h.y));             // (x0+x4,  x1+x5)
        u64 t2b = add2(pk(a.y, a.z), pk(a.w, h.x));    // (x1+x3,  x2+x4)

        #pragma unroll
        for (int d = 0; d < 5; d++) {
            const int o = r - 4 + d;                   // output row receiving
            if (o < 0 || o >= STRIP) continue;         // constant-folded
            const int k = 2 - ((d < 2) ? (2 - d) : (d - 2));  // 0,1,2,1,0
            const int s = o % 6;
            fma2(acc0[s], wp[k][0], t1a);
            fma2(acc0[s], wp[k][1], t2a);
            fma2(acc0[s], wp[k][2], p01);
            fma2(acc1[s], wp[k][0], t1b);
            fma2(acc1[s], wp[k][1], t2b);
            fma2(acc1[s], wp[k][2], p23);
        }

        const int o = r - 4;                           // row completed this iter
        if (o >= 0) {                                  // constant-folded
            const int s = o % 6;
            float2 lo = unpk(acc0[s]);
            float2 hi = unpk(acc1[s]);
            *(float4*)outp = make_float4(lo.x, lo.y, hi.x, hi.y);
            outp += WID;
            acc0[s] = 0ull; acc1[s] = 0ull;
        }
    }
}

extern "C" void kernel_launch(void* const* d_in, const int* in_sizes, int n_in,
                              void* d_out, int out_size) {
    const float* x     = (const float*)d_in[0];
    const float* logls = (const float*)d_in[1];
    float* out = (float*)d_out;

    blur_weights_kernel<<<1, 32>>>(logls);

    // 4096 images * 4 strips * 32 lanes = 524288 threads / 256 = 2048 blocks
    blur_main_kernel<<<2048, 256>>>(x, out);
}

// round 4
// speedup vs baseline: 2.4915x; 1.4244x over previous
#include <cuda_runtime.h>

// Depthwise 5x5 blur, x: (32,128,128,128) fp32 = 4096 images of 128x128.
// w[dy][dx] = exp(-((dy^2+dx^2)^2)/(2*exp(log_ls))), normalized. Fully symmetric:
// 3 distinct row-classes (k=|dy| mapped 2,1,0) x 3 col-classes.

#define RAD 2
#define WID 128
#define STRIP 32        // output rows per thread

typedef unsigned long long u64;

__device__ u64 g_wp[9];     // packed duplicated normalized weights [k*3+j]

__global__ void blur_weights_kernel(const float* __restrict__ logls) {
    __shared__ float wraw[25];
    int t = threadIdx.x;
    float ls = expf(logls[0]);
    if (t < 25) {
        int di = t / 5 - RAD;
        int dj = t % 5 - RAD;
        float d = (float)(di * di + dj * dj);
        wraw[t] = expf(-(d * d) / (2.0f * ls));
    }
    __syncthreads();
    if (t == 0) {
        float s = 0.0f;
        #pragma unroll
        for (int u = 0; u < 25; u++) s += wraw[u];
        float inv = 1.0f / s;
        #pragma unroll
        for (int k = 0; k < 3; k++) {
            #pragma unroll
            for (int j = 0; j < 3; j++) {
                float w = wraw[k * 5 + j] * inv;
                u64 p;
                asm("mov.b64 %0, {%1, %1};" : "=l"(p) : "f"(w));
                g_wp[k * 3 + j] = p;
            }
        }
    }
}

__device__ __forceinline__ u64 pk(float lo, float hi) {
    u64 r; asm("mov.b64 %0, {%1, %2};" : "=l"(r) : "f"(lo), "f"(hi)); return r;
}
__device__ __forceinline__ u64 add2(u64 a, u64 b) {
    u64 r; asm("add.rn.f32x2 %0, %1, %2;" : "=l"(r) : "l"(a), "l"(b)); return r;
}
__device__ __forceinline__ void fma2(u64& d, u64 a, u64 b) {
    asm("fma.rn.f32x2 %0, %1, %2, %0;" : "+l"(d) : "l"(a), "l"(b));
}
__device__ __forceinline__ float2 unpk(u64 a) {
    float2 v; asm("mov.b64 {%0, %1}, %2;" : "=f"(v.x), "=f"(v.y) : "l"(a)); return v;
}

// Thread layout: lane = tid&31 -> 4 output cols (c=lane*4);
// strip=(tid>>5)&3 -> 32 output rows; (tid>>7) -> image within block.
// 256 threads = 2 images/block, 2048 blocks, no shared memory.
__global__ void __launch_bounds__(256, 4)
blur_main_kernel(const float* __restrict__ x, float* __restrict__ out) {
    const int tid   = threadIdx.x;
    const int lane  = tid & 31;
    const int strip = (tid >> 5) & 3;
    const int img   = blockIdx.x * 2 + (tid >> 7);
    const int c     = lane * 4;
    const int row0  = strip * STRIP;

    u64 wp[9];
    #pragma unroll
    for (int u = 0; u < 9; u++) wp[u] = g_wp[u];

    const float* __restrict__ base = x + (size_t)img * (WID * WID);
    const float* rowp = base + (row0 - RAD) * WID + c;
    float*       outp = out + (size_t)img * (WID * WID) + row0 * WID + c;

    const bool has_l = (lane > 0);
    const bool has_h = (lane < 31);

    // Double-buffered row registers.
    float4 a[2];
    float2 l[2], h[2];

    // Load row r=0 (gr = row0-2).
    {
        const int gr = row0 - RAD;
        const bool vr = ((unsigned)gr < (unsigned)WID);
        a[0] = make_float4(0.f, 0.f, 0.f, 0.f);
        l[0] = make_float2(0.f, 0.f);
        h[0] = make_float2(0.f, 0.f);
        if (vr) {
            a[0] = *(const float4*)(rowp);
            if (has_l) l[0] = *(const float2*)(rowp - 2);
            if (has_h) h[0] = *(const float2*)(rowp + 4);
        }
        rowp += WID;
    }

    // Ring of 5 accumulator pairs.
    u64 acc0[5], acc1[5];
    #pragma unroll
    for (int i = 0; i < 5; i++) { acc0[i] = 0ull; acc1[i] = 0ull; }

    #pragma unroll
    for (int r = 0; r < STRIP + 4; r++) {
        const int cur = r & 1;
        const int nxt = cur ^ 1;

        // Prefetch row r+1 before computing row r.
        if (r < STRIP + 3) {
            const int gr = row0 + (r + 1) - RAD;
            const bool vr = ((unsigned)gr < (unsigned)WID);
            a[nxt] = make_float4(0.f, 0.f, 0.f, 0.f);
            l[nxt] = make_float2(0.f, 0.f);
            h[nxt] = make_float2(0.f, 0.f);
            if (vr) {
                a[nxt] = *(const float4*)(rowp);
                if (has_l) l[nxt] = *(const float2*)(rowp - 2);
                if (has_h) h[nxt] = *(const float2*)(rowp + 4);
            }
            rowp += WID;
        }

        // Horizontal pair-sums for cols (c,c+1) and (c+2,c+3).
        // x[-2..5] = l.x,l.y, a.x,a.y,a.z,a.w, h.x,h.y
        const float4 av = a[cur];
        const float2 lv = l[cur];
        const float2 hv = h[cur];
        u64 p01 = pk(av.x, av.y);
        u64 p23 = pk(av.z, av.w);
        u64 t1a = add2(pk(lv.x, lv.y), p23);              // (x-2+x2, x-1+x3)
        u64 t2a = add2(pk(lv.y, av.x), pk(av.y, av.z));   // (x-1+x1, x0+x2)
        u64 t1b = add2(p01, pk(hv.x, hv.y));              // (x0+x4,  x1+x5)
        u64 t2b = add2(pk(av.y, av.z), pk(av.w, hv.x));   // (x1+x3,  x2+x4)

        #pragma unroll
        for (int d = 0; d < 5; d++) {
            const int o = r - 4 + d;                      // receiving output row
            if (o < 0 || o >= STRIP) continue;            // constant-folded
            const int k = 2 - ((d < 2) ? (2 - d) : (d - 2));  // 0,1,2,1,0
            const int s = o % 5;
            fma2(acc0[s], wp[k * 3 + 0], t1a);
            fma2(acc0[s], wp[k * 3 + 1], t2a);
            fma2(acc0[s], wp[k * 3 + 2], p01);
            fma2(acc1[s], wp[k * 3 + 0], t1b);
            fma2(acc1[s], wp[k * 3 + 1], t2b);
            fma2(acc1[s], wp[k * 3 + 2], p23);
        }

        const int o = r - 4;                              // row completed now
        if (o >= 0) {                                     // constant-folded
            const int s = o % 5;
            float2 lo = unpk(acc0[s]);
            float2 hi = unpk(acc1[s]);
            *(float4*)outp = make_float4(lo.x, lo.y, hi.x, hi.y);
            outp += WID;
            acc0[s] = 0ull; acc1[s] = 0ull;
        }
    }
}

extern "C" void kernel_launch(void* const* d_in, const int* in_sizes, int n_in,
                              void* d_out, int out_size) {
    const float* x     = (const float*)d_in[0];
    const float* logls = (const float*)d_in[1];
    float* out = (float*)d_out;

    blur_weights_kernel<<<1, 32>>>(logls);

    blur_main_kernel<<<2048, 256>>>(x, out);
}

// round 5
// speedup vs baseline: 2.6688x; 1.0711x over previous
#include <cuda_runtime.h>

// Depthwise 5x5 blur, x: (32,128,128,128) fp32 = 4096 images of 128x128.
// w[dy][dx] = exp(-((dy^2+dx^2)^2)/(2*exp(log_ls))), normalized. Fully symmetric:
// 6 distinct exponentials (s = dy^2+dx^2 in {0,1,2,4,5,8}), 3x3 distinct weights.
// Single kernel: each thread derives the 9 packed weights itself (5 expf).
// Halo columns come from warp shuffles (1 LDG.128 per row per thread).

#define RAD 2
#define WID 128
#define STRIP 32        // output rows per thread
#define NROWS (STRIP + 4)

typedef unsigned long long u64;

__device__ __forceinline__ u64 pk(float lo, float hi) {
    u64 r; asm("mov.b64 %0, {%1, %2};" : "=l"(r) : "f"(lo), "f"(hi)); return r;
}
__device__ __forceinline__ u64 pk1(float v) {
    u64 r; asm("mov.b64 %0, {%1, %1};" : "=l"(r) : "f"(v)); return r;
}
__device__ __forceinline__ u64 add2(u64 a, u64 b) {
    u64 r; asm("add.rn.f32x2 %0, %1, %2;" : "=l"(r) : "l"(a), "l"(b)); return r;
}
__device__ __forceinline__ void fma2(u64& d, u64 a, u64 b) {
    asm("fma.rn.f32x2 %0, %1, %2, %0;" : "+l"(d) : "l"(a), "l"(b));
}
__device__ __forceinline__ float2 unpk(u64 a) {
    float2 v; asm("mov.b64 {%0, %1}, %2;" : "=f"(v.x), "=f"(v.y) : "l"(a)); return v;
}

// Thread layout: lane = tid&31 -> 4 output cols (c=lane*4);
// strip=(tid>>5)&3 -> 32 output rows; (tid>>7) -> image within block.
// 256 threads = 2 images/block, 2048 blocks, no shared memory.
__global__ void __launch_bounds__(256, 4)
blur_main_kernel(const float* __restrict__ x, float* __restrict__ out,
                 const float* __restrict__ logls) {
    const int tid   = threadIdx.x;
    const int lane  = tid & 31;
    const int strip = (tid >> 5) & 3;
    const int img   = blockIdx.x * 2 + (tid >> 7);
    const int c     = lane * 4;
    const int row0  = strip * STRIP;

    // ---- Per-thread weight table (5 expf, fully overlapped with prefetch) ----
    // s = dy^2+dx^2; w ~ exp(-s^2/(2*ls)); classes s in {0,1,2,4,5,8}.
    const float inv2ls = 0.5f * expf(-logls[0]);   // 1/(2*exp(logls))
    const float e1 = expf(-1.0f  * inv2ls);
    const float e2 = expf(-4.0f  * inv2ls);
    const float e4 = expf(-16.0f * inv2ls);
    const float e5 = expf(-25.0f * inv2ls);
    const float e8 = expf(-64.0f * inv2ls);
    const float inv = 1.0f / (1.0f + 4.0f * (e1 + e2 + e4 + e8) + 8.0f * e5);
    // wp[k][j]: k = row class (|dy|=2-k), j = col class (|dx|=2-j)
    u64 wp[9];
    wp[0] = pk1(e8 * inv); wp[1] = pk1(e5 * inv); wp[2] = pk1(e4 * inv);
    wp[3] = wp[1];         wp[4] = pk1(e2 * inv); wp[5] = pk1(e1 * inv);
    wp[6] = wp[2];         wp[7] = wp[5];         wp[8] = pk1(inv);

    const float* rowp = x + (size_t)img * (WID * WID) + (row0 - RAD) * WID + c;
    float*       outp = out + (size_t)img * (WID * WID) + row0 * WID + c;

    const bool has_l = (lane > 0);
    const bool has_h = (lane < 31);

    // Triple-buffered row registers (prefetch distance 2).
    float4 a[3];

    #pragma unroll
    for (int pr = 0; pr < 2; pr++) {
        const int gr = row0 + pr - RAD;
        a[pr] = make_float4(0.f, 0.f, 0.f, 0.f);
        if ((unsigned)gr < (unsigned)WID)
            a[pr] = *(const float4*)(rowp);
        rowp += WID;
    }

    // Ring of 5 accumulator pairs.
    u64 acc0[5], acc1[5];
    #pragma unroll
    for (int i = 0; i < 5; i++) { acc0[i] = 0ull; acc1[i] = 0ull; }

    #pragma unroll
    for (int r = 0; r < NROWS; r++) {
        // Prefetch row r+2.
        if (r + 2 < NROWS) {
            const int gr = row0 + (r + 2) - RAD;
            const int b  = (r + 2) % 3;
            a[b] = make_float4(0.f, 0.f, 0.f, 0.f);
            if ((unsigned)gr < (unsigned)WID)
                a[b] = *(const float4*)(rowp);
            rowp += WID;
        }

        const float4 av = a[r % 3];

        // Halo via warp shuffle: x[-2],x[-1] from lane-1; x[4],x[5] from lane+1.
        float slx = __shfl_up_sync(0xffffffffu, av.z, 1);
        float sly = __shfl_up_sync(0xffffffffu, av.w, 1);
        float shx = __shfl_down_sync(0xffffffffu, av.x, 1);
        float shy = __shfl_down_sync(0xffffffffu, av.y, 1);
        const float lx = has_l ? slx : 0.f;
        const float ly = has_l ? sly : 0.f;
        const float hx = has_h ? shx : 0.f;
        const float hy = has_h ? shy : 0.f;

        // Horizontal pair-sums for cols (c,c+1) and (c+2,c+3).
        // x[-2..5] = lx,ly, av.x,av.y,av.z,av.w, hx,hy
        u64 p01 = pk(av.x, av.y);
        u64 p23 = pk(av.z, av.w);
        u64 t1a = add2(pk(lx, ly), p23);                  // (x-2+x2, x-1+x3)
        u64 t2a = add2(pk(ly, av.x), pk(av.y, av.z));     // (x-1+x1, x0+x2)
        u64 t1b = add2(p01, pk(hx, hy));                  // (x0+x4,  x1+x5)
        u64 t2b = add2(pk(av.y, av.z), pk(av.w, hx));     // (x1+x3,  x2+x4)

        #pragma unroll
        for (int d = 0; d < 5; d++) {
            const int o = r - 4 + d;                      // receiving output row
            if (o < 0 || o >= STRIP) continue;            // constant-folded
            const int k = 2 - ((d < 2) ? (2 - d) : (d - 2));  // 0,1,2,1,0
            const int s = o % 5;
            fma2(acc0[s], wp[k * 3 + 0], t1a);
            fma2(acc0[s], wp[k * 3 + 1], t2a);
            fma2(acc0[s], wp[k * 3 + 2], p01);
            fma2(acc1[s], wp[k * 3 + 0], t1b);
            fma2(acc1[s], wp[k * 3 + 1], t2b);
            fma2(acc1[s], wp[k * 3 + 2], p23);
        }

        const int o = r - 4;                              // row completed now
        if (o >= 0) {                                     // constant-folded
            const int s = o % 5;
            float2 lo = unpk(acc0[s]);
            float2 hi = unpk(acc1[s]);
            *(float4*)outp = make_float4(lo.x, lo.y, hi.x, hi.y);
            outp += WID;
            acc0[s] = 0ull; acc1[s] = 0ull;
        }
    }
}

extern "C" void kernel_launch(void* const* d_in, const int* in_sizes, int n_in,
                              void* d_out, int out_size) {
    const float* x     = (const float*)d_in[0];
    const float* logls = (const float*)d_in[1];
    float* out = (float*)d_out;

    blur_main_kernel<<<2048, 256>>>(x, out, logls);
}

// round 6
// speedup vs baseline: 2.8568x; 1.0704x over previous
#include <cuda_runtime.h>

// Depthwise 5x5 blur, x: (32,128,128,128) fp32 = 4096 images of 128x128.
// w[dy][dx] = exp(-((dy^2+dx^2)^2)/(2*exp(log_ls))), normalized. Fully symmetric:
// 6 distinct exponentials (s = dy^2+dx^2 in {0,1,2,4,5,8}), 3x3 distinct weights.
// Single kernel, per-thread weight derivation (5 expf), shuffle halos,
// packed fma.rn.f32x2 arithmetic, 1x LDG.128 per row per thread.
// STRIP=16 -> 4096 blocks -> 6.9 waves (last wave 92% full): no tail idle.

#define RAD 2
#define WID 128
#define STRIP 16        // output rows per thread
#define NROWS (STRIP + 4)

typedef unsigned long long u64;

__device__ __forceinline__ u64 pk(float lo, float hi) {
    u64 r; asm("mov.b64 %0, {%1, %2};" : "=l"(r) : "f"(lo), "f"(hi)); return r;
}
__device__ __forceinline__ u64 pk1(float v) {
    u64 r; asm("mov.b64 %0, {%1, %1};" : "=l"(r) : "f"(v)); return r;
}
__device__ __forceinline__ u64 add2(u64 a, u64 b) {
    u64 r; asm("add.rn.f32x2 %0, %1, %2;" : "=l"(r) : "l"(a), "l"(b)); return r;
}
__device__ __forceinline__ void fma2(u64& d, u64 a, u64 b) {
    asm("fma.rn.f32x2 %0, %1, %2, %0;" : "+l"(d) : "l"(a), "l"(b));
}
__device__ __forceinline__ float2 unpk(u64 a) {
    float2 v; asm("mov.b64 {%0, %1}, %2;" : "=f"(v.x), "=f"(v.y) : "l"(a)); return v;
}

// Thread layout: lane = tid&31 -> 4 output cols (c=lane*4);
// strip = tid>>5 (0..7) -> 16 output rows. One image per 256-thread block.
// Grid = 4096 blocks. No shared memory.
__global__ void __launch_bounds__(256, 4)
blur_main_kernel(const float* __restrict__ x, float* __restrict__ out,
                 const float* __restrict__ logls) {
    const int tid   = threadIdx.x;
    const int lane  = tid & 31;
    const int strip = tid >> 5;
    const int img   = blockIdx.x;
    const int c     = lane * 4;
    const int row0  = strip * STRIP;

    // ---- Per-thread weight table (5 expf, overlapped with first prefetch) ----
    const float inv2ls = 0.5f * expf(-logls[0]);   // 1/(2*exp(logls))
    const float e1 = expf(-1.0f  * inv2ls);
    const float e2 = expf(-4.0f  * inv2ls);
    const float e4 = expf(-16.0f * inv2ls);
    const float e5 = expf(-25.0f * inv2ls);
    const float e8 = expf(-64.0f * inv2ls);
    const float inv = 1.0f / (1.0f + 4.0f * (e1 + e2 + e4 + e8) + 8.0f * e5);
    // wp[k*3+j]: k = row class (|dy|=2-k), j = col class (|dx|=2-j)
    u64 wp[9];
    wp[0] = pk1(e8 * inv); wp[1] = pk1(e5 * inv); wp[2] = pk1(e4 * inv);
    wp[3] = wp[1];         wp[4] = pk1(e2 * inv); wp[5] = pk1(e1 * inv);
    wp[6] = wp[2];         wp[7] = wp[5];         wp[8] = pk1(inv);

    const float* rowp = x + (size_t)img * (WID * WID) + (row0 - RAD) * WID + c;
    float*       outp = out + (size_t)img * (WID * WID) + row0 * WID + c;

    const bool has_l = (lane > 0);
    const bool has_h = (lane < 31);

    // Triple-buffered row registers (prefetch distance 2).
    float4 a[3];
    #pragma unroll
    for (int pr = 0; pr < 2; pr++) {
        const int gr = row0 + pr - RAD;
        a[pr] = make_float4(0.f, 0.f, 0.f, 0.f);
        if ((unsigned)gr < (unsigned)WID)
            a[pr] = *(const float4*)(rowp);
        rowp += WID;
    }

    // Ring of 5 accumulator pairs.
    u64 acc0[5], acc1[5];
    #pragma unroll
    for (int i = 0; i < 5; i++) { acc0[i] = 0ull; acc1[i] = 0ull; }

    #pragma unroll
    for (int r = 0; r < NROWS; r++) {
        // Prefetch row r+2.
        if (r + 2 < NROWS) {
            const int gr = row0 + (r + 2) - RAD;
            const int b  = (r + 2) % 3;
            a[b] = make_float4(0.f, 0.f, 0.f, 0.f);
            if ((unsigned)gr < (unsigned)WID)
                a[b] = *(const float4*)(rowp);
            rowp += WID;
        }

        const float4 av = a[r % 3];

        // Halo via warp shuffle: x[-2],x[-1] from lane-1; x[4],x[5] from lane+1.
        float slx = __shfl_up_sync(0xffffffffu, av.z, 1);
        float sly = __shfl_up_sync(0xffffffffu, av.w, 1);
        float shx = __shfl_down_sync(0xffffffffu, av.x, 1);
        float shy = __shfl_down_sync(0xffffffffu, av.y, 1);
        const float lx = has_l ? slx : 0.f;
        const float ly = has_l ? sly : 0.f;
        const float hx = has_h ? shx : 0.f;
        const float hy = has_h ? shy : 0.f;

        // Horizontal pair-sums for cols (c,c+1) and (c+2,c+3).
        // x[-2..5] = lx,ly, av.x,av.y,av.z,av.w, hx,hy
        u64 p01 = pk(av.x, av.y);
        u64 p23 = pk(av.z, av.w);
        u64 t1a = add2(pk(lx, ly), p23);                  // (x-2+x2, x-1+x3)
        u64 t2a = add2(pk(ly, av.x), pk(av.y, av.z));     // (x-1+x1, x0+x2)
        u64 t1b = add2(p01, pk(hx, hy));                  // (x0+x4,  x1+x5)
        u64 t2b = add2(pk(av.y, av.z), pk(av.w, hx));     // (x1+x3,  x2+x4)

        #pragma unroll
        for (int d = 0; d < 5; d++) {
            const int o = r - 4 + d;                      // receiving output row
            if (o < 0 || o >= STRIP) continue;            // constant-folded
            const int k = 2 - ((d < 2) ? (2 - d) : (d - 2));  // 0,1,2,1,0
            const int s = o % 5;
            fma2(acc0[s], wp[k * 3 + 0], t1a);
            fma2(acc0[s], wp[k * 3 + 1], t2a);
            fma2(acc0[s], wp[k * 3 + 2], p01);
            fma2(acc1[s], wp[k * 3 + 0], t1b);
            fma2(acc1[s], wp[k * 3 + 1], t2b);
            fma2(acc1[s], wp[k * 3 + 2], p23);
        }

        const int o = r - 4;                              // row completed now
        if (o >= 0) {                                     // constant-folded
            const int s = o % 5;
            float2 lo = unpk(acc0[s]);
            float2 hi = unpk(acc1[s]);
            __stcs((float4*)outp, make_float4(lo.x, lo.y, hi.x, hi.y));
            outp += WID;
            acc0[s] = 0ull; acc1[s] = 0ull;
        }
    }
}

extern "C" void kernel_launch(void* const* d_in, const int* in_sizes, int n_in,
                              void* d_out, int out_size) {
    const float* x     = (const float*)d_in[0];
    const float* logls = (const float*)d_in[1];
    float* out = (float*)d_out;

    blur_main_kernel<<<4096, 256>>>(x, out, logls);
}